// round 16
// baseline (speedup 1.0000x reference)
#include <cuda_runtime.h>

// Normalized correlation layer, GB300 sm_103a — round 16.
// Identity: sum((a-ma)(b-mb))/(sa*sb) = (S_ab - 25*ma*mb) * (1/sa)*(1/sb).
//
// Round-16 vs round-15: RHO-PAIR mainloop. A dup'd a-operand (dr,dc) now
// serves BOTH rhos of a pair step (d=r0-dr and d=r1-dr): dup instances
// 125 -> 75 per phase (-200 MOV/thread; alu pipe was 37.7%). Odd pb pairs
// built per-dc (transient regs). All indices compile-time. Everything
// else identical to the 117.9us round-15 kernel.

#define NB 16
#define NR 37

typedef unsigned long long u64;

__device__ __forceinline__ u64 fma2_(u64 a, u64 b, u64 c) {
    u64 d; asm("fma.rn.f32x2 %0, %1, %2, %3;" : "=l"(d) : "l"(a), "l"(b), "l"(c)); return d;
}
__device__ __forceinline__ u64 mul2_(u64 a, u64 b) {
    u64 d; asm("mul.rn.f32x2 %0, %1, %2;" : "=l"(d) : "l"(a), "l"(b)); return d;
}
__device__ __forceinline__ u64 pk2(float x, float y) {
    u64 r; asm("mov.b64 %0, {%1, %2};" : "=l"(r) : "f"(x), "f"(y)); return r;
}
__device__ __forceinline__ float2 upk2(u64 v) {
    float2 f; asm("mov.b64 {%0, %1}, %2;" : "=f"(f.x), "=f"(f.y) : "l"(v)); return f;
}

// ---------------------------------------------------------------------------
// Smem layout (bytes).  Total 97280 -> 2 CTAs/SM.
// ---------------------------------------------------------------------------
#define A1F_OFF    18432
#define SNA_OFF    31232
#define SRA_OFF    32768
#define SMB_OFF    34304
#define SRB_OFF    41984
#define STAGE_OFF  49664
#define STAGE_ROW  1984
#define SMEM_BYTES 97280

__global__ __launch_bounds__(384, 2) void nc_corr_kernel(
    const float* __restrict__ in1, const float* __restrict__ in2,
    float* __restrict__ out)
{
    extern __shared__ char smraw[];
    u64*   PBraw = (u64*)smraw;
    float* A1F   = (float*)(smraw + A1F_OFF);
    float* SNA   = (float*)(smraw + SNA_OFF);
    float* SRA   = (float*)(smraw + SRA_OFF);
    u64*   SMBp  = (u64*)(smraw + SMB_OFF);
    float* SMBf  = (float*)(smraw + SMB_OFF);
    u64*   SRBp  = (u64*)(smraw + SRB_OFF);
    float* SRBf  = (float*)(smraw + SRB_OFF);
    float* stage = (float*)(smraw + STAGE_OFF);

    const int r   = blockIdx.x;
    const int b   = blockIdx.y;
    const int chq = blockIdx.z;        // c-quarter: 0..3

    const int tid = threadIdx.x;
    const int c   = tid & 31;          // channel within quarter == lane
    const int w   = tid >> 5;          // 0..11
    const int jj  = w % 6;             // 0..5
    const int th  = w / 6;             // 0..1

    // ---- fills (linear tid) ----
    for (int i = tid; i < 9 * 8 * 32; i += 384) {
        int cc = i & 31, ii = (i >> 5) & 7, row = i >> 8;
        int irow = r + row - 4;
        float vlo = 0.f, vhi = 0.f;
        if ((unsigned)irow < 37u) {
            const float* base = in2 + ((b * 37 + irow) * 12) * 128 + chq * 32 + cc;
            int collo = 2 * ii - 2, colhi = 2 * ii - 1;
            if ((unsigned)collo < 12u) vlo = base[collo * 128];
            if ((unsigned)colhi < 12u) vhi = base[colhi * 128];
        }
        PBraw[i] = pk2(vlo, vhi);
    }
    for (int i = tid; i < 5 * 16 * 32; i += 384) {
        int cc = i & 31, col = (i >> 5) & 15, dr = i >> 9;
        int irow = r + dr - 2, icol = col - 2;
        float v = 0.f;
        if ((unsigned)irow < 37u && (unsigned)icol < 12u)
            v = in1[((b * 37 + irow) * 12 + icol) * 128 + chq * 32 + cc];
        A1F[(dr * 16 + col) * 40 + cc] = v;
    }
    __syncthreads();

    // ---- fused stats (all register arrays statically indexed) ----
    {
        const int js = w;              // 0..11, WARP-UNIFORM

        float s1 = 0.f, q1 = 0.f;
        #pragma unroll
        for (int dr = 0; dr < 5; dr++) {
            #pragma unroll
            for (int dc = 0; dc < 5; dc++) {
                float v = A1F[(dr * 16 + js + dc) * 40 + c];
                s1 += v; q1 = fmaf(v, v, q1);
            }
        }
        float m1 = s1 * 0.04f;
        SNA[js * 32 + c] = -25.0f * m1;
        SRA[js * 32 + c] = rsqrtf(fmaf(-m1, m1, q1 * 0.04f));

        float S[9], Q[9];
        const int p0 = js >> 1;
        #pragma unroll
        for (int rho = 0; rho < 9; rho++) {
            float2 e0 = upk2(PBraw[(rho * 8 + p0)     * 32 + c]);
            float2 e1 = upk2(PBraw[(rho * 8 + p0 + 1) * 32 + c]);
            float2 e2 = upk2(PBraw[(rho * 8 + p0 + 2) * 32 + c]);
            float s, q;
            if ((js & 1) == 0) {       // uniform branch
                s = e0.x + e0.y + e1.x + e1.y + e2.x;
                q = fmaf(e0.x, e0.x, fmaf(e0.y, e0.y,
                    fmaf(e1.x, e1.x, fmaf(e1.y, e1.y, e2.x * e2.x))));
            } else {
                s = e0.y + e1.x + e1.y + e2.x + e2.y;
                q = fmaf(e0.y, e0.y, fmaf(e1.x, e1.x,
                    fmaf(e1.y, e1.y, fmaf(e2.x, e2.x, e2.y * e2.y))));
            }
            S[rho] = s; Q[rho] = q;
        }
        #pragma unroll
        for (int d = 0; d < 5; d++) {
            float ss = S[d] + S[d + 1] + S[d + 2] + S[d + 3] + S[d + 4];
            float qq = Q[d] + Q[d + 1] + Q[d + 2] + Q[d + 3] + Q[d + 4];
            float m = ss * 0.04f;
            int fi = (((d * 6 + (js >> 1)) * 32 + c) << 1) + (js & 1);
            SMBf[fi] = m;
            SRBf[fi] = rsqrtf(fmaf(-m, m, qq * 0.04f));
        }
    }
    __syncthreads();

    #pragma unroll 1
    for (int ph = 0; ph < 2; ph++) {
        const int j = jj + 6 * ph;

        float a1f[5][5];
        u64 acc[5][3];
        #pragma unroll
        for (int d = 0; d < 5; d++)
            #pragma unroll
            for (int tt = 0; tt < 3; tt++) acc[d][tt] = 0ull;

        // Rho-pair mainloop: step s covers rho r0=2s and r1=2s+1 (s=4: r0=8
        // only). One a-dup serves d0=r0-dr AND d1=r1-dr. All compile-time.
        #pragma unroll
        for (int s = 0; s < 5; s++) {
            const int r0 = 2 * s, r1 = 2 * s + 1;

            // lazy a1f rows entering the window
            if (r0 < 5) {
                #pragma unroll
                for (int dc = 0; dc < 5; dc++)
                    a1f[r0][dc] = A1F[(r0 * 16 + j + dc) * 40 + c];
            }
            if (r1 < 5) {
                #pragma unroll
                for (int dc = 0; dc < 5; dc++)
                    a1f[r1][dc] = A1F[(r1 * 16 + j + dc) * 40 + c];
            }

            u64 e0[5], e1[5];
            #pragma unroll
            for (int q = 0; q < 5; q++)
                e0[q] = PBraw[(r0 * 8 + 3 * th + q) * 32 + c];
            if (s < 4) {
                #pragma unroll
                for (int q = 0; q < 5; q++)
                    e1[q] = PBraw[(r1 * 8 + 3 * th + q) * 32 + c];
            }

            #pragma unroll
            for (int dc = 0; dc < 5; dc++) {
                // pb values for x = 2tt+dc: even x -> e[x/2]; odd -> built.
                u64 p0[3], p1[3];
                #pragma unroll
                for (int tt = 0; tt < 3; tt++) {
                    const int x = 2 * tt + dc;
                    if ((x & 1) == 0) p0[tt] = e0[x >> 1];
                    else {
                        float2 lo = upk2(e0[x >> 1]);
                        float2 hi = upk2(e0[(x >> 1) + 1]);
                        p0[tt] = pk2(lo.y, hi.x);
                    }
                }
                if (s < 4) {
                    #pragma unroll
                    for (int tt = 0; tt < 3; tt++) {
                        const int x = 2 * tt + dc;
                        if ((x & 1) == 0) p1[tt] = e1[x >> 1];
                        else {
                            float2 lo = upk2(e1[x >> 1]);
                            float2 hi = upk2(e1[(x >> 1) + 1]);
                            p1[tt] = pk2(lo.y, hi.x);
                        }
                    }
                }

                #pragma unroll
                for (int dr = 0; dr < 5; dr++) {
                    const int d0 = r0 - dr;            // compile-time
                    const int d1 = r1 - dr;            // compile-time
                    const bool v0 = (d0 >= 0 && d0 < 5);
                    const bool v1 = (s < 4) && (d1 >= 0 && d1 < 5);
                    if (v0 || v1) {
                        const u64 a = pk2(a1f[dr][dc], a1f[dr][dc]);
                        if (v0) {
                            #pragma unroll
                            for (int tt = 0; tt < 3; tt++)
                                acc[d0][tt] = fma2_(a, p0[tt], acc[d0][tt]);
                        }
                        if (v1) {
                            #pragma unroll
                            for (int tt = 0; tt < 3; tt++)
                                acc[d1][tt] = fma2_(a, p1[tt], acc[d1][tt]);
                        }
                    }
                }
            }
        }

        // Epilogue: res = (S - 25*ma*mb) * ra * rb with slot-d stats;
        // row2 duplication (r=35,36): clamped d>=3 outputs res[d-2].
        const float na = SNA[j * 32 + c];
        const float ra = SRA[j * 32 + c];
        const u64 na2 = pk2(na, na);
        const u64 ra2 = pk2(ra, ra);
        float* srow = stage + jj * STAGE_ROW + c * 62 + 6 * th;

        u64 res1[3], res2[3];          // saved for clamp duplication
        #pragma unroll
        for (int d = 0; d < 5; d++) {
            const bool clamp = (d >= 3) && (r + d > 38);
            #pragma unroll
            for (int tt = 0; tt < 3; tt++) {
                u64 mbp = SMBp[(d * 6 + 3 * th + tt) * 32 + c];
                u64 rbp = SRBp[(d * 6 + 3 * th + tt) * 32 + c];
                u64 v = mul2_(fma2_(na2, mbp, acc[d][tt]), mul2_(ra2, rbp));
                if (d == 1) res1[tt] = v;
                if (d == 2) res2[tt] = v;
                if (d == 3 && clamp) v = res1[tt];
                if (d == 4 && clamp) v = res2[tt];
                *(u64*)(srow + 12 * d + 2 * tt) = v;
            }
        }
        __syncthreads();

        // Flush: 6 j-tiles, each 32c x 60w floats = 960 u64 in gmem order.
        // Stage u64 index (c,k) = c*31 + k; gmem u64 index = c*30 + k.
        // Index math kept inside the block (transient registers).
        {
            const int c1 = tid / 30,        k1 = tid - 30 * c1;
            const int g2 = tid + 384;
            const int c2 = g2 / 30,         k2 = g2 - 30 * c2;
            const int g3 = tid + 768;
            const int c3 = g3 / 30,         k3 = g3 - 30 * c3;

            u64* og0 = (u64*)(out + ((b * 37 + r) * 12 + 6 * ph) * 7680
                                  + chq * 1920);
            #pragma unroll 1
            for (int jl = 0; jl < 6; jl++) {
                const u64* st0 = (const u64*)(stage + jl * STAGE_ROW);
                u64* og = og0 + jl * 3840;
                og[c1 * 30 + k1] = st0[c1 * 31 + k1];
                og[c2 * 30 + k2] = st0[c2 * 31 + k2];
                if (tid < 192)
                    og[c3 * 30 + k3] = st0[c3 * 31 + k3];
            }
        }
        __syncthreads();
    }
}

// ---------------------------------------------------------------------------
extern "C" void kernel_launch(void* const* d_in, const int* in_sizes, int n_in,
                              void* d_out, int out_size)
{
    const float* in1 = (const float*)d_in[0];
    const float* in2 = (const float*)d_in[1];
    float* out = (float*)d_out;

    cudaFuncSetAttribute(nc_corr_kernel,
                         cudaFuncAttributeMaxDynamicSharedMemorySize, SMEM_BYTES);

    nc_corr_kernel<<<dim3(NR, NB, 4), 384, SMEM_BYTES>>>(in1, in2, out);
}

// round 17
// speedup vs baseline: 1.0963x; 1.0963x over previous
#include <cuda_runtime.h>

// Normalized correlation layer, GB300 sm_103a — round 17.
// Identity: sum((a-ma)(b-mb))/(sa*sb) = (S_ab - 25*ma*mb) * (1/sa)*(1/sb).
//
// Round-17 vs round-15 (mainloop/epilogue/flush per output identical):
//  - each CTA computes TWO consecutive rows r0=2*rp, r1=r0+1: PB slab 9->10
//    rows (8/9 overlap), A1F 5->6 rows, and img2 slot stats for BOTH r's
//    collapse to 6 shared window sums W[k]=S[k..k+4]. Fill+stats cost per
//    output ~halves (was ~15% of issue + fill crossbar); grid 2368 -> 1216.
//  - row offset rr enters only smem addressing (uniform base+const); all
//    register arrays stay compile-time indexed.

#define NB 16

typedef unsigned long long u64;

__device__ __forceinline__ u64 fma2_(u64 a, u64 b, u64 c) {
    u64 d; asm("fma.rn.f32x2 %0, %1, %2, %3;" : "=l"(d) : "l"(a), "l"(b), "l"(c)); return d;
}
__device__ __forceinline__ u64 mul2_(u64 a, u64 b) {
    u64 d; asm("mul.rn.f32x2 %0, %1, %2;" : "=l"(d) : "l"(a), "l"(b)); return d;
}
__device__ __forceinline__ u64 pk2(float x, float y) {
    u64 r; asm("mov.b64 %0, {%1, %2};" : "=l"(r) : "f"(x), "f"(y)); return r;
}
__device__ __forceinline__ float2 upk2(u64 v) {
    float2 f; asm("mov.b64 {%0, %1}, %2;" : "=f"(f.x), "=f"(f.y) : "l"(v)); return f;
}

// ---------------------------------------------------------------------------
// Smem layout (bytes).  Total 108032 -> 2 CTAs/SM.
//   PBraw u64[10][8][32]     natural col-pairs of padded img2 rows r0-4..r0+5
//   A1F   f32[6][16][40]     scalar padded img1 rows r0-2..r0+3
//   SNA/SRA  f32[2][12][32]  img1 stats (-25*mean, rstd) for r0, r1
//   SMBp/SRBp u64[6][6][32]  img2 window-k stats, j2-pair packed
//   stage f32[6][1984]       output staging (62-float c-stride)
// ---------------------------------------------------------------------------
#define A1F_OFF    20480
#define SNA_OFF    35840
#define SRA_OFF    38912
#define SMB_OFF    41984
#define SRB_OFF    51200
#define STAGE_OFF  60416
#define STAGE_ROW  1984
#define SMEM_BYTES 108032

__global__ __launch_bounds__(384, 2) void nc_corr_kernel(
    const float* __restrict__ in1, const float* __restrict__ in2,
    float* __restrict__ out)
{
    extern __shared__ char smraw[];
    u64*   PBraw = (u64*)smraw;
    float* A1F   = (float*)(smraw + A1F_OFF);
    float* SNA   = (float*)(smraw + SNA_OFF);
    float* SRA   = (float*)(smraw + SRA_OFF);
    u64*   SMBp  = (u64*)(smraw + SMB_OFF);
    float* SMBf  = (float*)(smraw + SMB_OFF);
    u64*   SRBp  = (u64*)(smraw + SRB_OFF);
    float* SRBf  = (float*)(smraw + SRB_OFF);
    float* stage = (float*)(smraw + STAGE_OFF);

    const int r0  = 2 * blockIdx.x;    // this CTA: rows r0 and r0+1 (if <=36)
    const int b   = blockIdx.y;
    const int chq = blockIdx.z;        // c-quarter: 0..3

    const int tid = threadIdx.x;
    const int c   = tid & 31;          // channel within quarter == lane
    const int w   = tid >> 5;          // 0..11
    const int jj  = w % 6;             // 0..5
    const int th  = w / 6;             // 0..1

    // ---- fills (linear tid) ----
    // PBraw[row][i][c] = (A2pad[2i], A2pad[2i+1]) for pad2 row r0+row, 10 rows.
    for (int i = tid; i < 10 * 8 * 32; i += 384) {
        int cc = i & 31, ii = (i >> 5) & 7, row = i >> 8;
        int irow = r0 + row - 4;
        float vlo = 0.f, vhi = 0.f;
        if ((unsigned)irow < 37u) {
            const float* base = in2 + ((b * 37 + irow) * 12) * 128 + chq * 32 + cc;
            int collo = 2 * ii - 2, colhi = 2 * ii - 1;
            if ((unsigned)collo < 12u) vlo = base[collo * 128];
            if ((unsigned)colhi < 12u) vhi = base[colhi * 128];
        }
        PBraw[i] = pk2(vlo, vhi);
    }
    // A1F[dr][col][c-pad40] = scalar f32 image1 value, pad1 row r0+dr, 6 rows.
    for (int i = tid; i < 6 * 16 * 32; i += 384) {
        int cc = i & 31, col = (i >> 5) & 15, dr = i >> 9;
        int irow = r0 + dr - 2, icol = col - 2;
        float v = 0.f;
        if ((unsigned)irow < 37u && (unsigned)icol < 12u)
            v = in1[((b * 37 + irow) * 12 + icol) * 128 + chq * 32 + cc];
        A1F[(dr * 16 + col) * 40 + cc] = v;
    }
    __syncthreads();

    // ---- fused stats (all register arrays statically indexed) ----
    {
        const int js = w;              // 0..11, WARP-UNIFORM

        // img1 stats for rr = 0, 1 (rows rr..rr+4 of the 6-row slab).
        #pragma unroll
        for (int rr = 0; rr < 2; rr++) {
            float s1 = 0.f, q1 = 0.f;
            #pragma unroll
            for (int dr = 0; dr < 5; dr++) {
                #pragma unroll
                for (int dc = 0; dc < 5; dc++) {
                    float v = A1F[((rr + dr) * 16 + js + dc) * 40 + c];
                    s1 += v; q1 = fmaf(v, v, q1);
                }
            }
            float m1 = s1 * 0.04f;
            SNA[(rr * 12 + js) * 32 + c] = -25.0f * m1;
            SRA[(rr * 12 + js) * 32 + c] = rsqrtf(fmaf(-m1, m1, q1 * 0.04f));
        }

        // img2 per-rho window sums over all 10 slab rows.
        float S[10], Q[10];
        const int p0 = js >> 1;
        #pragma unroll
        for (int rho = 0; rho < 10; rho++) {
            float2 e0 = upk2(PBraw[(rho * 8 + p0)     * 32 + c]);
            float2 e1 = upk2(PBraw[(rho * 8 + p0 + 1) * 32 + c]);
            float2 e2 = upk2(PBraw[(rho * 8 + p0 + 2) * 32 + c]);
            float s, q;
            if ((js & 1) == 0) {       // uniform branch
                s = e0.x + e0.y + e1.x + e1.y + e2.x;
                q = fmaf(e0.x, e0.x, fmaf(e0.y, e0.y,
                    fmaf(e1.x, e1.x, fmaf(e1.y, e1.y, e2.x * e2.x))));
            } else {
                s = e0.y + e1.x + e1.y + e2.x + e2.y;
                q = fmaf(e0.y, e0.y, fmaf(e1.x, e1.x,
                    fmaf(e1.y, e1.y, fmaf(e2.x, e2.x, e2.y * e2.y))));
            }
            S[rho] = s; Q[rho] = q;
        }
        // Shared window stats W[k] = rows k..k+4; slot d of r0 is k=d,
        // slot d of r1 is k=d+1.
        #pragma unroll
        for (int k = 0; k < 6; k++) {
            float ss = S[k] + S[k + 1] + S[k + 2] + S[k + 3] + S[k + 4];
            float qq = Q[k] + Q[k + 1] + Q[k + 2] + Q[k + 3] + Q[k + 4];
            float m = ss * 0.04f;
            int fi = (((k * 6 + (js >> 1)) * 32 + c) << 1) + (js & 1);
            SMBf[fi] = m;
            SRBf[fi] = rsqrtf(fmaf(-m, m, qq * 0.04f));
        }
    }
    __syncthreads();

    #pragma unroll 1
    for (int rr = 0; rr < 2; rr++) {
        const int r = r0 + rr;
        if (rr == 1 && r > 36) break;

        #pragma unroll 1
        for (int ph = 0; ph < 2; ph++) {
            const int j = jj + 6 * ph;

            float a1f[5][5];
            u64 acc[5][3];
            #pragma unroll
            for (int d = 0; d < 5; d++)
                #pragma unroll
                for (int tt = 0; tt < 3; tt++) acc[d][tt] = 0ull;

            // Static rho loop; row offsets shifted by uniform rr.
            #pragma unroll
            for (int rho = 0; rho < 9; rho++) {
                if (rho < 5) {
                    #pragma unroll
                    for (int dc = 0; dc < 5; dc++)
                        a1f[rho][dc] = A1F[((rr + rho) * 16 + j + dc) * 40 + c];
                }
                u64 e[5];
                #pragma unroll
                for (int q = 0; q < 5; q++)
                    e[q] = PBraw[((rr + rho) * 8 + 3 * th + q) * 32 + c];

                u64 pb[9];
                #pragma unroll
                for (int m = 0; m < 5; m++) pb[2 * m] = e[m];
                #pragma unroll
                for (int m = 0; m < 4; m++) {
                    float2 lo = upk2(e[m]);
                    float2 hi = upk2(e[m + 1]);
                    pb[2 * m + 1] = pk2(lo.y, hi.x);
                }

                #pragma unroll
                for (int d = 0; d < 5; d++) {
                    const int dr = rho - d;                 // compile-time
                    if (dr >= 0 && dr < 5) {
                        #pragma unroll
                        for (int dc = 0; dc < 5; dc++) {
                            const u64 a = pk2(a1f[dr][dc], a1f[dr][dc]);
                            #pragma unroll
                            for (int tt = 0; tt < 3; tt++)
                                acc[d][tt] = fma2_(a, pb[2 * tt + dc], acc[d][tt]);
                        }
                    }
                }
            }

            // Epilogue: res = (S - 25*ma*mb) * ra * rb, window k = d + rr;
            // row2 duplication (r=35,36): clamped d>=3 outputs res[d-2].
            const float na = SNA[(rr * 12 + j) * 32 + c];
            const float ra = SRA[(rr * 12 + j) * 32 + c];
            const u64 na2 = pk2(na, na);
            const u64 ra2 = pk2(ra, ra);
            float* srow = stage + jj * STAGE_ROW + c * 62 + 6 * th;

            u64 res1[3], res2[3];          // saved for clamp duplication
            #pragma unroll
            for (int d = 0; d < 5; d++) {
                const bool clamp = (d >= 3) && (r + d > 38);
                #pragma unroll
                for (int tt = 0; tt < 3; tt++) {
                    u64 mbp = SMBp[((d + rr) * 6 + 3 * th + tt) * 32 + c];
                    u64 rbp = SRBp[((d + rr) * 6 + 3 * th + tt) * 32 + c];
                    u64 v = mul2_(fma2_(na2, mbp, acc[d][tt]), mul2_(ra2, rbp));
                    if (d == 1) res1[tt] = v;
                    if (d == 2) res2[tt] = v;
                    if (d == 3 && clamp) v = res1[tt];
                    if (d == 4 && clamp) v = res2[tt];
                    *(u64*)(srow + 12 * d + 2 * tt) = v;
                }
            }
            __syncthreads();

            // Flush: 6 j-tiles, each 32c x 60w floats = 960 u64 in gmem
            // order. Stage u64 index (c,k) = c*31 + k; gmem = c*30 + k.
            {
                const int c1 = tid / 30,        k1 = tid - 30 * c1;
                const int g2 = tid + 384;
                const int c2 = g2 / 30,         k2 = g2 - 30 * c2;
                const int g3 = tid + 768;
                const int c3 = g3 / 30,         k3 = g3 - 30 * c3;

                u64* og0 = (u64*)(out + ((b * 37 + r) * 12 + 6 * ph) * 7680
                                      + chq * 1920);
                #pragma unroll 1
                for (int jl = 0; jl < 6; jl++) {
                    const u64* st0 = (const u64*)(stage + jl * STAGE_ROW);
                    u64* og = og0 + jl * 3840;
                    og[c1 * 30 + k1] = st0[c1 * 31 + k1];
                    og[c2 * 30 + k2] = st0[c2 * 31 + k2];
                    if (tid < 192)
                        og[c3 * 30 + k3] = st0[c3 * 31 + k3];
                }
            }
            __syncthreads();
        }
    }
}

// ---------------------------------------------------------------------------
extern "C" void kernel_launch(void* const* d_in, const int* in_sizes, int n_in,
                              void* d_out, int out_size)
{
    const float* in1 = (const float*)d_in[0];
    const float* in2 = (const float*)d_in[1];
    float* out = (float*)d_out;

    cudaFuncSetAttribute(nc_corr_kernel,
                         cudaFuncAttributeMaxDynamicSharedMemorySize, SMEM_BYTES);

    nc_corr_kernel<<<dim3(19, NB, 4), 384, SMEM_BYTES>>>(in1, in2, out);
}